// round 16
// baseline (speedup 1.0000x reference)
#include <cuda_runtime.h>
#include <cuda_bf16.h>
#include <cstdint>

#define BATCH      131072
#define HID        256
#define SPIKE_DIM  128
#define COORD_DIM  64
#define IN_DIM     192
#define NUM_STEPS  25
#define BETA       0.7f
#define OMB        (1.0f - BETA)

#define TILES      (BATCH / 128)   // 1024
#define NBLK       148
#define XP         100             // u32 stride per X row (96 used; 100%32==4 -> LDSM conflict-free)
#define WP         100
#define DELTA      0.004f          // rigorous bf16 Cauchy-Schwarz error coefficient

// ---------------- device scratch ----------------
__device__ unsigned g_W0b2[HID * WP];          // W0 bf16x2, [j][k2], padded stride
__device__ float    g_W0T[IN_DIM * HID];       // W0T[k][j] = W0[j][k]  (coalesced heavy path)
__device__ float    g_wn[HID];                 // ||W0 row j||_2
__device__ float    g_W1T[HID * HID];          // W1T[j][i] = W1[i][j]
__device__ float    g_WcT[HID * COORD_DIM];    // WcT[i][m] = W_out[128+m][i]
__device__ unsigned g_wmax_u, g_bmax_u;        // monotone max (replay-safe)
__device__ int      g_heavy[BATCH];
__device__ int      g_nheavy;

// ---------------- helpers ----------------
__device__ __forceinline__ uint32_t smem_u32(const void* p) {
    uint32_t a;
    asm("{ .reg .u64 t; cvta.to.shared.u64 t, %1; cvt.u32.u64 %0, t; }" : "=r"(a) : "l"(p));
    return a;
}
__device__ __forceinline__ unsigned pk2(float lo, float hi) {
    unsigned r;
    asm("cvt.rn.bf16x2.f32 %0, %1, %2;" : "=r"(r) : "f"(hi), "f"(lo));
    return r;
}
__device__ __forceinline__ void mma16816(float c[4], const unsigned a[4], const unsigned b[2]) {
    asm volatile(
        "mma.sync.aligned.m16n8k16.row.col.f32.bf16.bf16.f32 "
        "{%0,%1,%2,%3}, {%4,%5,%6,%7}, {%8,%9}, {%0,%1,%2,%3};"
        : "+f"(c[0]), "+f"(c[1]), "+f"(c[2]), "+f"(c[3])
        : "r"(a[0]), "r"(a[1]), "r"(a[2]), "r"(a[3]), "r"(b[0]), "r"(b[1]));
}
__device__ __forceinline__ void ldsm4(uint32_t r[4], uint32_t addr) {
    asm volatile("ldmatrix.sync.aligned.m8n8.x4.shared.b16 {%0,%1,%2,%3}, [%4];"
        : "=r"(r[0]), "=r"(r[1]), "=r"(r[2]), "=r"(r[3]) : "r"(addr));
}
__device__ __forceinline__ float wgt(float c) {
    float d = fmaxf(1.0f - 0.3f * c, 0.2101f);
    return fminf(__fdividef(0.70007f * c, d), 3.3334f);
}

// ---------------- prep: 129 blocks of 32x32 tile transposes (parallel + coalesced) ----------------
// b in [0,64)    : W1 tile (tr=b>>3, tc=b&7) -> W1T, + wmax partial
// b in [64,112)  : W0T tile (tk=(b-64)/8, tj=(b-64)%8) -> W0T + bf16x2 pack
// b in [112,128) : WcT tile (ti=(b-112)>>3, tjj=(b-112)&7)
// b == 128       : row norms + b1max + g_nheavy reset
__global__ void k_prep(const float* __restrict__ W0, const float* __restrict__ W1,
                       const float* __restrict__ b1, const float* __restrict__ W_out) {
    __shared__ float sm[32 * 33];
    __shared__ float red[8];
    int b    = blockIdx.x;
    int tid  = threadIdx.x;
    int lane = tid & 31;
    int w    = tid >> 5;

    if (b < 64) {
        // ---- W1 32x32 tile transpose + wmax
        int R = (b >> 3) * 32, C = (b & 7) * 32;
        float m = 0.0f;
        #pragma unroll
        for (int rr = 0; rr < 4; rr++) {
            int r = w * 4 + rr;
            float v = W1[(size_t)(R + r) * HID + C + lane];
            sm[r * 33 + lane] = v;
            m = fmaxf(m, fabsf(v));
        }
        #pragma unroll
        for (int o = 16; o; o >>= 1) m = fmaxf(m, __shfl_xor_sync(~0u, m, o));
        if (lane == 0) red[w] = m;
        __syncthreads();
        if (tid == 0) {
            float t = fmaxf(fmaxf(fmaxf(red[0], red[1]), fmaxf(red[2], red[3])),
                            fmaxf(fmaxf(red[4], red[5]), fmaxf(red[6], red[7])));
            atomicMax(&g_wmax_u, __float_as_uint(t));
        }
        #pragma unroll
        for (int rr = 0; rr < 4; rr++) {
            int j = C + w * 4 + rr;
            g_W1T[(size_t)j * HID + R + lane] = sm[lane * 33 + w * 4 + rr];
        }
    } else if (b < 112) {
        // ---- W0 tile: k cols [32tk,+32) x j rows [32tj,+32) -> W0T + pack
        int idx = b - 64;
        int kb = (idx >> 3) * 32, jb = (idx & 7) * 32;
        #pragma unroll
        for (int rr = 0; rr < 4; rr++) {
            int r = w * 4 + rr;   // j-local
            sm[r * 33 + lane] = W0[(size_t)(jb + r) * IN_DIM + kb + lane];
        }
        __syncthreads();
        #pragma unroll
        for (int rr = 0; rr < 4; rr++) {
            int k = kb + w * 4 + rr;
            g_W0T[(size_t)k * HID + jb + lane] = sm[lane * 33 + w * 4 + rr];
        }
        // bf16x2 pack: 32 rows x 16 k2 = 512 elems, 2 per thread
        #pragma unroll
        for (int p = 0; p < 2; p++) {
            int e  = p * 256 + tid;
            int jr = e >> 4, k2 = e & 15;
            g_W0b2[(size_t)(jb + jr) * WP + (kb >> 1) + k2] =
                pk2(sm[jr * 33 + 2 * k2], sm[jr * 33 + 2 * k2 + 1]);
        }
    } else if (b < 128) {
        // ---- WcT tile: i cols [32ti,+32) x j rows [32tjj,+32)
        int idx = b - 112;
        int ib = (idx >> 3) * 32, jb = (idx & 7) * 32;
        #pragma unroll
        for (int rr = 0; rr < 4; rr++) {
            int r = w * 4 + rr;   // i-local
            sm[r * 33 + lane] = W_out[(size_t)(SPIKE_DIM + ib + r) * HID + jb + lane];
        }
        __syncthreads();
        #pragma unroll
        for (int rr = 0; rr < 4; rr++) {
            int j = jb + w * 4 + rr;
            g_WcT[(size_t)j * COORD_DIM + ib + lane] = sm[lane * 33 + w * 4 + rr];
        }
    } else {
        // ---- norms + b1max + reset
        if (tid == 0) g_nheavy = 0;
        #pragma unroll 1
        for (int r = 0; r < 32; r++) {
            int j = w + 8 * r;    // rows strided across warps
            float sq = 0.0f;
            #pragma unroll
            for (int mseg = 0; mseg < 6; mseg++) {
                float v = W0[(size_t)j * IN_DIM + lane + 32 * mseg];
                sq = fmaf(v, v, sq);
            }
            #pragma unroll
            for (int o = 16; o; o >>= 1) sq += __shfl_xor_sync(~0u, sq, o);
            if (lane == 0) g_wn[j] = sqrtf(sq);
        }
        float bb = fabsf(b1[tid]);
        #pragma unroll
        for (int o = 16; o; o >>= 1) bb = fmaxf(bb, __shfl_xor_sync(~0u, bb, o));
        if (lane == 0) red[w] = bb;
        __syncthreads();
        if (tid == 0) {
            float t = fmaxf(fmaxf(fmaxf(red[0], red[1]), fmaxf(red[2], red[3])),
                            fmaxf(fmaxf(red[4], red[5]), fmaxf(red[6], red[7])));
            atomicMax(&g_bmax_u, __float_as_uint(t));
        }
    }
}

// ---------------- GEMM: 1024 threads, kk-outer single pass, A loaded once ----------------
#define U_WS  0
#define U_X0  25600
#define U_X1  38400
#define U_B0  51200
#define U_WN  51456
#define U_TH  51712
#define U_BC  51968
#define U_XN  52032          // [3][128]
#define U_SS  52416          // [2][128]
#define GEMM_SMEM (52672 * 4)

__global__ __launch_bounds__(1024, 1)
void k_gemm(const float* __restrict__ spikes, const float* __restrict__ coords,
            const float* __restrict__ b0, const float* __restrict__ b_out,
            float* __restrict__ out) {
    extern __shared__ unsigned sh[];
    unsigned* Ws  = sh + U_WS;
    float*    b0s = (float*)(sh + U_B0);
    float*    wns = (float*)(sh + U_WN);
    float*    ths = (float*)(sh + U_TH);
    float*    bcs = (float*)(sh + U_BC);
    float*    xn2 = (float*)(sh + U_XN);   // [3][128]
    float*    Ss  = (float*)(sh + U_SS);   // [2][128]

    int tid  = threadIdx.x;
    int lane = tid & 31;
    int wid  = tid >> 5;
    int g    = lane >> 2, qp = lane & 3;
    int wm   = wid >> 3,  wn_ = wid & 7;

    {
        const float4* src = (const float4*)g_W0b2;
        float4* dst = (float4*)Ws;
        #pragma unroll
        for (int i = 0; i < 7; i++) {
            int idx = i * 1024 + tid;
            if (idx < 6400) dst[idx] = src[idx];
        }
        if (tid < 256) {
            float b = b0[tid];
            b0s[tid] = b;
            ths[tid] = 0.9999f - b;
            wns[tid] = g_wn[tid];
            Ss[tid]  = 0.0f;
        }
        if (tid < 384) xn2[tid] = 0.0f;
        if (tid < 64)  bcs[tid] = b_out[SPIKE_DIM + tid];
    }

    float Slim;
    {
        float wmax = __uint_as_float(g_wmax_u);
        float bmax = __uint_as_float(g_bmax_u);
        if (bmax >= 0.999f)    Slim = -1.0f;
        else if (wmax <= 0.0f) Slim = 1e30f;
        else Slim = __fdividef(0.999f - bmax, 0.3000001f * wmax) * 0.998f - 0.01f;
    }

    uint32_t xb[2]  = { smem_u32(sh + U_X0), smem_u32(sh + U_X1) };
    uint32_t a_off  = (uint32_t)(((wm * 32 + (lane & 15)) * XP + ((lane >> 4) << 2)) * 4);
    uint32_t b_base = smem_u32(Ws)
                    + (uint32_t)((((lane >> 4) * 8 + (lane & 7)) * WP + (((lane >> 3) & 1) << 2)) * 4)
                    + (uint32_t)((wn_ * 32) * WP * 4);

    __syncthreads();

    {
        int R0 = blockIdx.x * 128;
        unsigned* Xs = sh + U_X0;
        #pragma unroll
        for (int it = 0; it < 6; it++) {
            int idx = it * 1024 + tid;
            int row = idx / 48, f4 = idx % 48;
            float4 v;
            if (f4 < 32) v = ((const float4*)(spikes + (size_t)(R0 + row) * SPIKE_DIM))[f4];
            else         v = ((const float4*)(coords + (size_t)(R0 + row) * COORD_DIM))[f4 - 32];
            *(uint2*)(Xs + row * XP + 2 * f4) = make_uint2(pk2(v.x, v.y), pk2(v.z, v.w));
            float sq = fmaf(v.x, v.x, fmaf(v.y, v.y, fmaf(v.z, v.z, v.w * v.w)));
            #pragma unroll
            for (int o = 8; o; o >>= 1) sq += __shfl_xor_sync(~0u, sq, o);
            if ((lane & 15) == 0) atomicAdd(&xn2[row], sq);
        }
    }
    __syncthreads();

    int i = 0;
    #pragma unroll 1
    for (int t = blockIdx.x; t < TILES; t += NBLK, i++) {
        int R0 = t * 128;
        int tn = t + NBLK;
        bool hn = (tn < TILES);
        int Rn = tn * 128;
        int cur = i & 1;
        int rb = i % 3, wb = (i + 1) % 3, zb = (i + 2) % 3;
        int sb = i & 1;
        unsigned* Xn  = sh + (cur ? U_X0 : U_X1);
        float*    xnn = xn2 + wb * 128;

        if (tid < 128) xn2[zb * 128 + tid] = 0.0f;

        float4 pf[2];
        if (hn) {
            #pragma unroll
            for (int it = 0; it < 2; it++) {
                int idx = it * 1024 + tid;
                int row = idx / 48, f4 = idx % 48;
                if (f4 < 32) pf[it] = __ldg((const float4*)(spikes + (size_t)(Rn + row) * SPIKE_DIM) + f4);
                else         pf[it] = __ldg((const float4*)(coords + (size_t)(Rn + row) * COORD_DIM) + (f4 - 32));
            }
        }

        float4 z = make_float4(0.f, 0.f, 0.f, 0.f);
        #pragma unroll
        for (int it = 0; it < 8; it++) {
            int idx = it * 1024 + tid;
            int row = idx >> 6, f = idx & 63;
            __stcs((float4*)(out + (size_t)(R0 + row) * HID) + f, z);
        }
        #pragma unroll
        for (int it = 0; it < 2; it++) {
            int idx = it * 1024 + tid;
            int row = idx >> 4, f = idx & 15;
            float4 cv = make_float4(bcs[4 * f], bcs[4 * f + 1], bcs[4 * f + 2], bcs[4 * f + 3]);
            __stcs((float4*)(out + (size_t)BATCH * HID + (size_t)(R0 + row) * COORD_DIM) + f, cv);
        }

        uint32_t a_base = xb[cur] + a_off;

        float cf[2][4][4];
        #pragma unroll
        for (int mt = 0; mt < 2; mt++)
            #pragma unroll
            for (int nt = 0; nt < 4; nt++)
                #pragma unroll
                for (int q = 0; q < 4; q++) cf[mt][nt][q] = 0.0f;

        #pragma unroll
        for (int s = 0; s < 3; s++) {
            #pragma unroll
            for (int k4 = 0; k4 < 4; k4++) {
                int kk = s * 4 + k4;
                uint32_t a[2][4], bfr[2][4];
                #pragma unroll
                for (int mt = 0; mt < 2; mt++)
                    ldsm4(a[mt], a_base + (unsigned)((mt * 16 * XP + kk * 8) * 4));
                #pragma unroll
                for (int np = 0; np < 2; np++)
                    ldsm4(bfr[np], b_base + (unsigned)((np * 16 * WP + kk * 8) * 4));
                #pragma unroll
                for (int mt = 0; mt < 2; mt++)
                    #pragma unroll
                    for (int nt = 0; nt < 4; nt++)
                        mma16816(cf[mt][nt], a[mt], &bfr[nt >> 1][(nt & 1) * 2]);
            }
            if (hn) {
                #pragma unroll
                for (int it = 0; it < 2; it++) {
                    int idx = (s * 2 + it) * 1024 + tid;
                    int row = idx / 48, f4 = idx % 48;
                    float4 v = pf[it];
                    *(uint2*)(Xn + row * XP + 2 * f4) = make_uint2(pk2(v.x, v.y), pk2(v.z, v.w));
                    float sq = fmaf(v.x, v.x, fmaf(v.y, v.y, fmaf(v.z, v.z, v.w * v.w)));
                    #pragma unroll
                    for (int o = 8; o; o >>= 1) sq += __shfl_xor_sync(~0u, sq, o);
                    if ((lane & 15) == 0) atomicAdd(&xnn[row], sq);
                }
                if (s < 2) {
                    #pragma unroll
                    for (int it = 0; it < 2; it++) {
                        int idx = ((s + 1) * 2 + it) * 1024 + tid;
                        int row = idx / 48, f4 = idx % 48;
                        if (f4 < 32) pf[it] = __ldg((const float4*)(spikes + (size_t)(Rn + row) * SPIKE_DIM) + f4);
                        else         pf[it] = __ldg((const float4*)(coords + (size_t)(Rn + row) * COORD_DIM) + (f4 - 32));
                    }
                }
            }
        }

        const float* xn = xn2 + rb * 128;
        float dx0[2], dx1[2];
        #pragma unroll
        for (int mt = 0; mt < 2; mt++) {
            int r0 = wm * 32 + mt * 16 + g;
            dx0[mt] = DELTA * sqrtf(xn[r0]);
            dx1[mt] = DELTA * sqrtf(xn[r0 + 8]);
        }
        float sl0[2] = {0.f, 0.f}, sl1[2] = {0.f, 0.f};
        #pragma unroll
        for (int nt = 0; nt < 4; nt++) {
            int c = wn_ * 32 + nt * 8 + 2 * qp;
            float tA = ths[c], tB = ths[c + 1];
            float wA = wns[c], wB = wns[c + 1];
            #pragma unroll
            for (int mt = 0; mt < 2; mt++) {
                float u0 = fmaf(dx0[mt], wA, cf[mt][nt][0]);
                float u1 = fmaf(dx0[mt], wB, cf[mt][nt][1]);
                float u2 = fmaf(dx1[mt], wA, cf[mt][nt][2]);
                float u3 = fmaf(dx1[mt], wB, cf[mt][nt][3]);
                if (u0 >= tA) sl0[mt] += wgt(u0 + b0s[c]);
                if (u1 >= tB) sl0[mt] += wgt(u1 + b0s[c + 1]);
                if (u2 >= tA) sl1[mt] += wgt(u2 + b0s[c]);
                if (u3 >= tB) sl1[mt] += wgt(u3 + b0s[c + 1]);
            }
        }

        #pragma unroll
        for (int mt = 0; mt < 2; mt++) {
            float s0 = sl0[mt], s1 = sl1[mt];
            s0 += __shfl_xor_sync(~0u, s0, 1); s0 += __shfl_xor_sync(~0u, s0, 2);
            s1 += __shfl_xor_sync(~0u, s1, 1); s1 += __shfl_xor_sync(~0u, s1, 2);
            if (qp == 0) {
                int r0 = wm * 32 + mt * 16 + g;
                if (s0 > 0.f) atomicAdd(&Ss[sb * 128 + r0], s0);
                if (s1 > 0.f) atomicAdd(&Ss[sb * 128 + r0 + 8], s1);
            }
        }
        __syncthreads();

        if (tid < 128) {
            float s = Ss[sb * 128 + tid];
            if (s >= Slim) {
                int pos = atomicAdd(&g_nheavy, 1);
                g_heavy[pos] = R0 + tid;
            }
            Ss[sb * 128 + tid] = 0.0f;
        }
    }
}

// ---------------- heavy rows: exact fp32 recompute (coalesced) + simulation ----------------
__global__ void k_heavy(const float* __restrict__ spikes, const float* __restrict__ coords,
                        const float* __restrict__ b0, const float* __restrict__ b1,
                        const float* __restrict__ b_out, float* __restrict__ out) {
    int warps = (gridDim.x * blockDim.x) >> 5;
    int gw    = (blockIdx.x * blockDim.x + threadIdx.x) >> 5;
    int lane  = threadIdx.x & 31;
    int n     = g_nheavy;

    for (int idx = gw; idx < n; idx += warps) {
        int row = g_heavy[idx];
        float* actp = out + (size_t)row * HID;
        float* crdp = out + (size_t)BATCH * HID + (size_t)row * COORD_DIM;

        const float* xs = spikes + (size_t)row * SPIKE_DIM;
        const float* xc = coords + (size_t)row * COORD_DIM;
        float s[8];
        #pragma unroll
        for (int r = 0; r < 8; r++) s[r] = 0.0f;
        #pragma unroll 4
        for (int k = 0; k < SPIKE_DIM; k++) {
            float xv = xs[k];
            const float* wr = g_W0T + (size_t)k * HID;
            #pragma unroll
            for (int r = 0; r < 8; r++) s[r] = fmaf(xv, wr[lane + 32 * r], s[r]);
        }
        #pragma unroll 4
        for (int k = 0; k < COORD_DIM; k++) {
            float xv = xc[k];
            const float* wr = g_W0T + (size_t)(SPIKE_DIM + k) * HID;
            #pragma unroll
            for (int r = 0; r < 8; r++) s[r] = fmaf(xv, wr[lane + 32 * r], s[r]);
        }

        float q[8], v0[8], v1[8], b1v[8];
        #pragma unroll
        for (int k = 0; k < 8; k++) {
            q[k] = OMB * (s[k] + b0[lane + 32 * k]);
            v0[k] = 0.0f; v1[k] = 0.0f;
            b1v[k] = b1[lane + 32 * k];
        }
        unsigned sp1m[8];
        #pragma unroll
        for (int k = 0; k < 8; k++) sp1m[k] = 0u;

        #pragma unroll 1
        for (int t = 0; t < NUM_STEPS; t++) {
            unsigned act[8];
            #pragma unroll
            for (int k = 0; k < 8; k++) {
                v0[k] = fmaf(BETA, v0[k], q[k]);
                bool sp = (v0[k] >= 1.0f);
                act[k] = __ballot_sync(~0u, sp);
                if (sp) v0[k] = 0.0f;
            }
            float c1[8];
            #pragma unroll
            for (int k = 0; k < 8; k++) c1[k] = b1v[k];
            #pragma unroll
            for (int k = 0; k < 8; k++) {
                unsigned m = act[k];
                while (m) {
                    int j = 32 * k + __ffs(m) - 1;
                    m &= m - 1;
                    const float* wr = g_W1T + (size_t)j * HID;
                    #pragma unroll
                    for (int r = 0; r < 8; r++) c1[r] += wr[lane + 32 * r];
                }
            }
            #pragma unroll
            for (int k = 0; k < 8; k++) {
                v1[k] = fmaf(BETA, v1[k], OMB * c1[k]);
                bool sp = (v1[k] >= 1.0f);
                unsigned b = __ballot_sync(~0u, sp);
                if (t == NUM_STEPS - 1) sp1m[k] = b;
                if (sp) v1[k] = 0.0f;
            }
        }

        #pragma unroll
        for (int k = 0; k < 8; k++)
            actp[lane + 32 * k] = ((sp1m[k] >> lane) & 1u) ? 1.0f : 0.0f;

        float ca = b_out[SPIKE_DIM + lane];
        float cb = b_out[SPIKE_DIM + 32 + lane];
        #pragma unroll
        for (int k = 0; k < 8; k++) {
            unsigned m = sp1m[k];
            while (m) {
                int i = 32 * k + __ffs(m) - 1;
                m &= m - 1;
                ca += g_WcT[(size_t)i * COORD_DIM + lane];
                cb += g_WcT[(size_t)i * COORD_DIM + 32 + lane];
            }
        }
        crdp[lane]      = ca;
        crdp[lane + 32] = cb;
    }
}

// ---------------- launch ----------------
extern "C" void kernel_launch(void* const* d_in, const int* in_sizes, int n_in,
                              void* d_out, int out_size) {
    const float* spikes = (const float*)d_in[0];
    const float* coords = (const float*)d_in[1];
    const float* W0     = (const float*)d_in[2];
    const float* b0     = (const float*)d_in[3];
    const float* W1     = (const float*)d_in[4];
    const float* b1     = (const float*)d_in[5];
    const float* W_out  = (const float*)d_in[6];
    const float* b_out  = (const float*)d_in[7];
    float* out = (float*)d_out;

    k_prep<<<129, 256>>>(W0, W1, b1, W_out);

    cudaFuncSetAttribute(k_gemm, cudaFuncAttributeMaxDynamicSharedMemorySize, GEMM_SMEM);
    k_gemm<<<NBLK, 1024, GEMM_SMEM>>>(spikes, coords, b0, b_out, out);

    k_heavy<<<148, 256>>>(spikes, coords, b0, b1, b_out, out);
}

// round 17
// speedup vs baseline: 1.0870x; 1.0870x over previous
#include <cuda_runtime.h>
#include <cuda_bf16.h>
#include <cstdint>

#define BATCH      131072
#define HID        256
#define SPIKE_DIM  128
#define COORD_DIM  64
#define IN_DIM     192
#define NUM_STEPS  25
#define BETA       0.7f
#define OMB        (1.0f - BETA)

#define TILES      (BATCH / 128)   // 1024
#define NBLK       148
#define XP         100             // u32 stride per X row (96 used; 100%32==4 -> LDSM conflict-free)
#define WP         100
#define DELTA      0.004f          // rigorous bf16 Cauchy-Schwarz error coefficient

// ---------------- device scratch ----------------
__device__ unsigned g_W0b2[HID * WP];          // W0 bf16x2, [j][k2], padded stride
__device__ float    g_W0T[IN_DIM * HID];       // W0T[k][j] = W0[j][k]  (coalesced heavy path)
__device__ float    g_wn[HID];                 // ||W0 row j||_2
__device__ float    g_W1T[HID * HID];          // W1T[j][i] = W1[i][j]
__device__ float    g_WcT[HID * COORD_DIM];    // WcT[i][m] = W_out[128+m][i]
__device__ unsigned g_wmax_u, g_bmax_u;        // monotone max (replay-safe)
__device__ int      g_heavy[BATCH];
__device__ int      g_nheavy;

// ---------------- helpers ----------------
__device__ __forceinline__ uint32_t smem_u32(const void* p) {
    uint32_t a;
    asm("{ .reg .u64 t; cvta.to.shared.u64 t, %1; cvt.u32.u64 %0, t; }" : "=r"(a) : "l"(p));
    return a;
}
__device__ __forceinline__ unsigned pk2(float lo, float hi) {
    unsigned r;
    asm("cvt.rn.bf16x2.f32 %0, %1, %2;" : "=r"(r) : "f"(hi), "f"(lo));
    return r;
}
__device__ __forceinline__ void mma16816(float c[4], const unsigned a[4], const unsigned b[2]) {
    asm volatile(
        "mma.sync.aligned.m16n8k16.row.col.f32.bf16.bf16.f32 "
        "{%0,%1,%2,%3}, {%4,%5,%6,%7}, {%8,%9}, {%0,%1,%2,%3};"
        : "+f"(c[0]), "+f"(c[1]), "+f"(c[2]), "+f"(c[3])
        : "r"(a[0]), "r"(a[1]), "r"(a[2]), "r"(a[3]), "r"(b[0]), "r"(b[1]));
}
__device__ __forceinline__ void ldsm4(uint32_t r[4], uint32_t addr) {
    asm volatile("ldmatrix.sync.aligned.m8n8.x4.shared.b16 {%0,%1,%2,%3}, [%4];"
        : "=r"(r[0]), "=r"(r[1]), "=r"(r[2]), "=r"(r[3]) : "r"(addr));
}
__device__ __forceinline__ float wgt(float c) {
    float d = fmaxf(1.0f - 0.3f * c, 0.2101f);
    return fminf(__fdividef(0.70007f * c, d), 3.3334f);
}

// ---------------- prep: 136 blocks, no serial latency chains ----------------
// b in [0,64)    : W1 32x32 tile transpose -> W1T, + wmax partial
// b in [64,112)  : W0 tile -> W0T + bf16x2 pack
// b in [112,128) : WcT tile
// b in [128,136) : row norms (32 rows each, 4/warp); b==128 also b1max + reset
__global__ void k_prep(const float* __restrict__ W0, const float* __restrict__ W1,
                       const float* __restrict__ b1, const float* __restrict__ W_out) {
    __shared__ float sm[32 * 33];
    __shared__ float red[8];
    int b    = blockIdx.x;
    int tid  = threadIdx.x;
    int lane = tid & 31;
    int w    = tid >> 5;

    if (b < 64) {
        int R = (b >> 3) * 32, C = (b & 7) * 32;
        float m = 0.0f;
        #pragma unroll
        for (int rr = 0; rr < 4; rr++) {
            int r = w * 4 + rr;
            float v = W1[(size_t)(R + r) * HID + C + lane];
            sm[r * 33 + lane] = v;
            m = fmaxf(m, fabsf(v));
        }
        #pragma unroll
        for (int o = 16; o; o >>= 1) m = fmaxf(m, __shfl_xor_sync(~0u, m, o));
        if (lane == 0) red[w] = m;
        __syncthreads();
        if (tid == 0) {
            float t = fmaxf(fmaxf(fmaxf(red[0], red[1]), fmaxf(red[2], red[3])),
                            fmaxf(fmaxf(red[4], red[5]), fmaxf(red[6], red[7])));
            atomicMax(&g_wmax_u, __float_as_uint(t));
        }
        #pragma unroll
        for (int rr = 0; rr < 4; rr++) {
            int j = C + w * 4 + rr;
            g_W1T[(size_t)j * HID + R + lane] = sm[lane * 33 + w * 4 + rr];
        }
    } else if (b < 112) {
        int idx = b - 64;
        int kb = (idx >> 3) * 32, jb = (idx & 7) * 32;
        #pragma unroll
        for (int rr = 0; rr < 4; rr++) {
            int r = w * 4 + rr;   // j-local
            sm[r * 33 + lane] = W0[(size_t)(jb + r) * IN_DIM + kb + lane];
        }
        __syncthreads();
        #pragma unroll
        for (int rr = 0; rr < 4; rr++) {
            int k = kb + w * 4 + rr;
            g_W0T[(size_t)k * HID + jb + lane] = sm[lane * 33 + w * 4 + rr];
        }
        #pragma unroll
        for (int p = 0; p < 2; p++) {
            int e  = p * 256 + tid;
            int jr = e >> 4, k2 = e & 15;
            g_W0b2[(size_t)(jb + jr) * WP + (kb >> 1) + k2] =
                pk2(sm[jr * 33 + 2 * k2], sm[jr * 33 + 2 * k2 + 1]);
        }
    } else if (b < 128) {
        int idx = b - 112;
        int ib = (idx >> 3) * 32, jb = (idx & 7) * 32;
        #pragma unroll
        for (int rr = 0; rr < 4; rr++) {
            int r = w * 4 + rr;   // i-local
            sm[r * 33 + lane] = W_out[(size_t)(SPIKE_DIM + ib + r) * HID + jb + lane];
        }
        __syncthreads();
        #pragma unroll
        for (int rr = 0; rr < 4; rr++) {
            int j = jb + w * 4 + rr;
            g_WcT[(size_t)j * COORD_DIM + ib + lane] = sm[lane * 33 + w * 4 + rr];
        }
    } else {
        // ---- norms: 8 blocks x 32 rows, 4 rows per warp (short chains only)
        int base = (b - 128) * 32;
        #pragma unroll
        for (int rr = 0; rr < 4; rr++) {
            int j = base + w * 4 + rr;
            float sq = 0.0f;
            #pragma unroll
            for (int mseg = 0; mseg < 6; mseg++) {
                float v = W0[(size_t)j * IN_DIM + lane + 32 * mseg];
                sq = fmaf(v, v, sq);
            }
            #pragma unroll
            for (int o = 16; o; o >>= 1) sq += __shfl_xor_sync(~0u, sq, o);
            if (lane == 0) g_wn[j] = sqrtf(sq);
        }
        if (b == 128) {
            if (tid == 0) g_nheavy = 0;
            float bb = fabsf(b1[tid]);
            #pragma unroll
            for (int o = 16; o; o >>= 1) bb = fmaxf(bb, __shfl_xor_sync(~0u, bb, o));
            if (lane == 0) red[w] = bb;
            __syncthreads();
            if (tid == 0) {
                float t = fmaxf(fmaxf(fmaxf(red[0], red[1]), fmaxf(red[2], red[3])),
                                fmaxf(fmaxf(red[4], red[5]), fmaxf(red[6], red[7])));
                atomicMax(&g_bmax_u, __float_as_uint(t));
            }
        }
    }
}

// ---------------- GEMM: 1024 threads, kk-outer single pass, A loaded once ----------------
#define U_WS  0
#define U_X0  25600
#define U_X1  38400
#define U_B0  51200
#define U_WN  51456
#define U_TH  51712
#define U_BC  51968
#define U_XN  52032          // [3][128]
#define U_SS  52416          // [2][128]
#define GEMM_SMEM (52672 * 4)

__global__ __launch_bounds__(1024, 1)
void k_gemm(const float* __restrict__ spikes, const float* __restrict__ coords,
            const float* __restrict__ b0, const float* __restrict__ b_out,
            float* __restrict__ out) {
    extern __shared__ unsigned sh[];
    unsigned* Ws  = sh + U_WS;
    float*    b0s = (float*)(sh + U_B0);
    float*    wns = (float*)(sh + U_WN);
    float*    ths = (float*)(sh + U_TH);
    float*    bcs = (float*)(sh + U_BC);
    float*    xn2 = (float*)(sh + U_XN);   // [3][128]
    float*    Ss  = (float*)(sh + U_SS);   // [2][128]

    int tid  = threadIdx.x;
    int lane = tid & 31;
    int wid  = tid >> 5;
    int g    = lane >> 2, qp = lane & 3;
    int wm   = wid >> 3,  wn_ = wid & 7;

    {
        const float4* src = (const float4*)g_W0b2;
        float4* dst = (float4*)Ws;
        #pragma unroll
        for (int i = 0; i < 7; i++) {
            int idx = i * 1024 + tid;
            if (idx < 6400) dst[idx] = src[idx];
        }
        if (tid < 256) {
            float b = b0[tid];
            b0s[tid] = b;
            ths[tid] = 0.9999f - b;
            wns[tid] = g_wn[tid];
            Ss[tid]  = 0.0f;
        }
        if (tid < 384) xn2[tid] = 0.0f;
        if (tid < 64)  bcs[tid] = b_out[SPIKE_DIM + tid];
    }

    float Slim;
    {
        float wmax = __uint_as_float(g_wmax_u);
        float bmax = __uint_as_float(g_bmax_u);
        if (bmax >= 0.999f)    Slim = -1.0f;
        else if (wmax <= 0.0f) Slim = 1e30f;
        else Slim = __fdividef(0.999f - bmax, 0.3000001f * wmax) * 0.998f - 0.01f;
    }

    uint32_t xb[2]  = { smem_u32(sh + U_X0), smem_u32(sh + U_X1) };
    uint32_t a_off  = (uint32_t)(((wm * 32 + (lane & 15)) * XP + ((lane >> 4) << 2)) * 4);
    uint32_t b_base = smem_u32(Ws)
                    + (uint32_t)((((lane >> 4) * 8 + (lane & 7)) * WP + (((lane >> 3) & 1) << 2)) * 4)
                    + (uint32_t)((wn_ * 32) * WP * 4);

    __syncthreads();

    {
        int R0 = blockIdx.x * 128;
        unsigned* Xs = sh + U_X0;
        #pragma unroll
        for (int it = 0; it < 6; it++) {
            int idx = it * 1024 + tid;
            int row = idx / 48, f4 = idx % 48;
            float4 v;
            if (f4 < 32) v = ((const float4*)(spikes + (size_t)(R0 + row) * SPIKE_DIM))[f4];
            else         v = ((const float4*)(coords + (size_t)(R0 + row) * COORD_DIM))[f4 - 32];
            *(uint2*)(Xs + row * XP + 2 * f4) = make_uint2(pk2(v.x, v.y), pk2(v.z, v.w));
            float sq = fmaf(v.x, v.x, fmaf(v.y, v.y, fmaf(v.z, v.z, v.w * v.w)));
            #pragma unroll
            for (int o = 8; o; o >>= 1) sq += __shfl_xor_sync(~0u, sq, o);
            if ((lane & 15) == 0) atomicAdd(&xn2[row], sq);
        }
    }
    __syncthreads();

    int i = 0;
    #pragma unroll 1
    for (int t = blockIdx.x; t < TILES; t += NBLK, i++) {
        int R0 = t * 128;
        int tn = t + NBLK;
        bool hn = (tn < TILES);
        int Rn = tn * 128;
        int cur = i & 1;
        int rb = i % 3, wb = (i + 1) % 3, zb = (i + 2) % 3;
        int sb = i & 1;
        unsigned* Xn  = sh + (cur ? U_X0 : U_X1);
        float*    xnn = xn2 + wb * 128;

        if (tid < 128) xn2[zb * 128 + tid] = 0.0f;

        float4 pf[2];
        if (hn) {
            #pragma unroll
            for (int it = 0; it < 2; it++) {
                int idx = it * 1024 + tid;
                int row = idx / 48, f4 = idx % 48;
                if (f4 < 32) pf[it] = __ldg((const float4*)(spikes + (size_t)(Rn + row) * SPIKE_DIM) + f4);
                else         pf[it] = __ldg((const float4*)(coords + (size_t)(Rn + row) * COORD_DIM) + (f4 - 32));
            }
        }

        float4 z = make_float4(0.f, 0.f, 0.f, 0.f);
        #pragma unroll
        for (int it = 0; it < 8; it++) {
            int idx = it * 1024 + tid;
            int row = idx >> 6, f = idx & 63;
            __stcs((float4*)(out + (size_t)(R0 + row) * HID) + f, z);
        }
        #pragma unroll
        for (int it = 0; it < 2; it++) {
            int idx = it * 1024 + tid;
            int row = idx >> 4, f = idx & 15;
            float4 cv = make_float4(bcs[4 * f], bcs[4 * f + 1], bcs[4 * f + 2], bcs[4 * f + 3]);
            __stcs((float4*)(out + (size_t)BATCH * HID + (size_t)(R0 + row) * COORD_DIM) + f, cv);
        }

        uint32_t a_base = xb[cur] + a_off;

        float cf[2][4][4];
        #pragma unroll
        for (int mt = 0; mt < 2; mt++)
            #pragma unroll
            for (int nt = 0; nt < 4; nt++)
                #pragma unroll
                for (int q = 0; q < 4; q++) cf[mt][nt][q] = 0.0f;

        #pragma unroll
        for (int s = 0; s < 3; s++) {
            #pragma unroll
            for (int k4 = 0; k4 < 4; k4++) {
                int kk = s * 4 + k4;
                uint32_t a[2][4], bfr[2][4];
                #pragma unroll
                for (int mt = 0; mt < 2; mt++)
                    ldsm4(a[mt], a_base + (unsigned)((mt * 16 * XP + kk * 8) * 4));
                #pragma unroll
                for (int np = 0; np < 2; np++)
                    ldsm4(bfr[np], b_base + (unsigned)((np * 16 * WP + kk * 8) * 4));
                #pragma unroll
                for (int mt = 0; mt < 2; mt++)
                    #pragma unroll
                    for (int nt = 0; nt < 4; nt++)
                        mma16816(cf[mt][nt], a[mt], &bfr[nt >> 1][(nt & 1) * 2]);
            }
            if (hn) {
                #pragma unroll
                for (int it = 0; it < 2; it++) {
                    int idx = (s * 2 + it) * 1024 + tid;
                    int row = idx / 48, f4 = idx % 48;
                    float4 v = pf[it];
                    *(uint2*)(Xn + row * XP + 2 * f4) = make_uint2(pk2(v.x, v.y), pk2(v.z, v.w));
                    float sq = fmaf(v.x, v.x, fmaf(v.y, v.y, fmaf(v.z, v.z, v.w * v.w)));
                    #pragma unroll
                    for (int o = 8; o; o >>= 1) sq += __shfl_xor_sync(~0u, sq, o);
                    if ((lane & 15) == 0) atomicAdd(&xnn[row], sq);
                }
                if (s < 2) {
                    #pragma unroll
                    for (int it = 0; it < 2; it++) {
                        int idx = ((s + 1) * 2 + it) * 1024 + tid;
                        int row = idx / 48, f4 = idx % 48;
                        if (f4 < 32) pf[it] = __ldg((const float4*)(spikes + (size_t)(Rn + row) * SPIKE_DIM) + f4);
                        else         pf[it] = __ldg((const float4*)(coords + (size_t)(Rn + row) * COORD_DIM) + (f4 - 32));
                    }
                }
            }
        }

        const float* xn = xn2 + rb * 128;
        float dx0[2], dx1[2];
        #pragma unroll
        for (int mt = 0; mt < 2; mt++) {
            int r0 = wm * 32 + mt * 16 + g;
            dx0[mt] = DELTA * sqrtf(xn[r0]);
            dx1[mt] = DELTA * sqrtf(xn[r0 + 8]);
        }
        float sl0[2] = {0.f, 0.f}, sl1[2] = {0.f, 0.f};
        #pragma unroll
        for (int nt = 0; nt < 4; nt++) {
            int c = wn_ * 32 + nt * 8 + 2 * qp;
            float tA = ths[c], tB = ths[c + 1];
            float wA = wns[c], wB = wns[c + 1];
            #pragma unroll
            for (int mt = 0; mt < 2; mt++) {
                float u0 = fmaf(dx0[mt], wA, cf[mt][nt][0]);
                float u1 = fmaf(dx0[mt], wB, cf[mt][nt][1]);
                float u2 = fmaf(dx1[mt], wA, cf[mt][nt][2]);
                float u3 = fmaf(dx1[mt], wB, cf[mt][nt][3]);
                if (u0 >= tA) sl0[mt] += wgt(u0 + b0s[c]);
                if (u1 >= tB) sl0[mt] += wgt(u1 + b0s[c + 1]);
                if (u2 >= tA) sl1[mt] += wgt(u2 + b0s[c]);
                if (u3 >= tB) sl1[mt] += wgt(u3 + b0s[c + 1]);
            }
        }

        #pragma unroll
        for (int mt = 0; mt < 2; mt++) {
            float s0 = sl0[mt], s1 = sl1[mt];
            s0 += __shfl_xor_sync(~0u, s0, 1); s0 += __shfl_xor_sync(~0u, s0, 2);
            s1 += __shfl_xor_sync(~0u, s1, 1); s1 += __shfl_xor_sync(~0u, s1, 2);
            if (qp == 0) {
                int r0 = wm * 32 + mt * 16 + g;
                if (s0 > 0.f) atomicAdd(&Ss[sb * 128 + r0], s0);
                if (s1 > 0.f) atomicAdd(&Ss[sb * 128 + r0 + 8], s1);
            }
        }
        __syncthreads();

        if (tid < 128) {
            float s = Ss[sb * 128 + tid];
            if (s >= Slim) {
                int pos = atomicAdd(&g_nheavy, 1);
                g_heavy[pos] = R0 + tid;
            }
            Ss[sb * 128 + tid] = 0.0f;
        }
    }
}

// ---------------- heavy rows: exact fp32 recompute (coalesced) + simulation ----------------
__global__ void k_heavy(const float* __restrict__ spikes, const float* __restrict__ coords,
                        const float* __restrict__ b0, const float* __restrict__ b1,
                        const float* __restrict__ b_out, float* __restrict__ out) {
    int warps = (gridDim.x * blockDim.x) >> 5;
    int gw    = (blockIdx.x * blockDim.x + threadIdx.x) >> 5;
    int lane  = threadIdx.x & 31;
    int n     = g_nheavy;

    for (int idx = gw; idx < n; idx += warps) {
        int row = g_heavy[idx];
        float* actp = out + (size_t)row * HID;
        float* crdp = out + (size_t)BATCH * HID + (size_t)row * COORD_DIM;

        const float* xs = spikes + (size_t)row * SPIKE_DIM;
        const float* xc = coords + (size_t)row * COORD_DIM;
        float s[8];
        #pragma unroll
        for (int r = 0; r < 8; r++) s[r] = 0.0f;
        #pragma unroll 4
        for (int k = 0; k < SPIKE_DIM; k++) {
            float xv = xs[k];
            const float* wr = g_W0T + (size_t)k * HID;
            #pragma unroll
            for (int r = 0; r < 8; r++) s[r] = fmaf(xv, wr[lane + 32 * r], s[r]);
        }
        #pragma unroll 4
        for (int k = 0; k < COORD_DIM; k++) {
            float xv = xc[k];
            const float* wr = g_W0T + (size_t)(SPIKE_DIM + k) * HID;
            #pragma unroll
            for (int r = 0; r < 8; r++) s[r] = fmaf(xv, wr[lane + 32 * r], s[r]);
        }

        float q[8], v0[8], v1[8], b1v[8];
        #pragma unroll
        for (int k = 0; k < 8; k++) {
            q[k] = OMB * (s[k] + b0[lane + 32 * k]);
            v0[k] = 0.0f; v1[k] = 0.0f;
            b1v[k] = b1[lane + 32 * k];
        }
        unsigned sp1m[8];
        #pragma unroll
        for (int k = 0; k < 8; k++) sp1m[k] = 0u;

        #pragma unroll 1
        for (int t = 0; t < NUM_STEPS; t++) {
            unsigned act[8];
            #pragma unroll
            for (int k = 0; k < 8; k++) {
                v0[k] = fmaf(BETA, v0[k], q[k]);
                bool sp = (v0[k] >= 1.0f);
                act[k] = __ballot_sync(~0u, sp);
                if (sp) v0[k] = 0.0f;
            }
            float c1[8];
            #pragma unroll
            for (int k = 0; k < 8; k++) c1[k] = b1v[k];
            #pragma unroll
            for (int k = 0; k < 8; k++) {
                unsigned m = act[k];
                while (m) {
                    int j = 32 * k + __ffs(m) - 1;
                    m &= m - 1;
                    const float* wr = g_W1T + (size_t)j * HID;
                    #pragma unroll
                    for (int r = 0; r < 8; r++) c1[r] += wr[lane + 32 * r];
                }
            }
            #pragma unroll
            for (int k = 0; k < 8; k++) {
                v1[k] = fmaf(BETA, v1[k], OMB * c1[k]);
                bool sp = (v1[k] >= 1.0f);
                unsigned b = __ballot_sync(~0u, sp);
                if (t == NUM_STEPS - 1) sp1m[k] = b;
                if (sp) v1[k] = 0.0f;
            }
        }

        #pragma unroll
        for (int k = 0; k < 8; k++)
            actp[lane + 32 * k] = ((sp1m[k] >> lane) & 1u) ? 1.0f : 0.0f;

        float ca = b_out[SPIKE_DIM + lane];
        float cb = b_out[SPIKE_DIM + 32 + lane];
        #pragma unroll
        for (int k = 0; k < 8; k++) {
            unsigned m = sp1m[k];
            while (m) {
                int i = 32 * k + __ffs(m) - 1;
                m &= m - 1;
                ca += g_WcT[(size_t)i * COORD_DIM + lane];
                cb += g_WcT[(size_t)i * COORD_DIM + 32 + lane];
            }
        }
        crdp[lane]      = ca;
        crdp[lane + 32] = cb;
    }
}

// ---------------- launch ----------------
extern "C" void kernel_launch(void* const* d_in, const int* in_sizes, int n_in,
                              void* d_out, int out_size) {
    const float* spikes = (const float*)d_in[0];
    const float* coords = (const float*)d_in[1];
    const float* W0     = (const float*)d_in[2];
    const float* b0     = (const float*)d_in[3];
    const float* W1     = (const float*)d_in[4];
    const float* b1     = (const float*)d_in[5];
    const float* W_out  = (const float*)d_in[6];
    const float* b_out  = (const float*)d_in[7];
    float* out = (float*)d_out;

    k_prep<<<136, 256>>>(W0, W1, b1, W_out);

    cudaFuncSetAttribute(k_gemm, cudaFuncAttributeMaxDynamicSharedMemorySize, GEMM_SMEM);
    k_gemm<<<NBLK, 1024, GEMM_SMEM>>>(spikes, coords, b0, b_out, out);

    k_heavy<<<148, 256>>>(spikes, coords, b0, b1, b_out, out);
}